// round 2
// baseline (speedup 1.0000x reference)
#include <cuda_runtime.h>

#define N_NODES 50000
#define D_FEAT 64
#define HIDDEN 128
#define N_EDGES 800000

// Scratch for aggregated neighbor features (no cudaMalloc allowed).
__device__ float g_neigh[N_NODES * D_FEAT];

__global__ void zero_neigh() {
    int i = blockIdx.x * blockDim.x + threadIdx.x;
    if (i < N_NODES * D_FEAT / 4)
        reinterpret_cast<float4*>(g_neigh)[i] = make_float4(0.f, 0.f, 0.f, 0.f);
}

// 16 threads per edge; each thread moves one float4 (4 feats) and does 4 REDs.
// NOTE: edge_index is int32 (JAX x64-disabled downcasts int64 -> int32).
__global__ void scatter_add(const float* __restrict__ x,
                            const int* __restrict__ ei) {
    int tid = blockIdx.x * blockDim.x + threadIdx.x;
    int e = tid >> 4;
    if (e >= N_EDGES) return;
    int c = tid & 15;
    int src = ei[e];
    int dst = ei[N_EDGES + e];
    float4 v = reinterpret_cast<const float4*>(x)[src * 16 + c];
    float* o = g_neigh + dst * 64 + c * 4;
    atomicAdd(o + 0, v.x);
    atomicAdd(o + 1, v.y);
    atomicAdd(o + 2, v.z);
    atomicAdd(o + 3, v.w);
}

// ---------------- fused concat + GEMM + bias + ReLU ----------------
// Tile: 64 nodes x 128 outputs per block, 256 threads.
// smem holds both operands transposed (k-major) so the inner k-loop does
// conflict-free float4 LDS for both H and W.
#define TM 64
#define HPAD 68   // 64 nodes + pad (stride stays 16B-multiple)
#define WPAD 132  // 128 outs + pad (stride stays 16B-multiple)

extern __shared__ float smem[];

__global__ void __launch_bounds__(256, 2) fused_gemm(
    const float* __restrict__ x, const float* __restrict__ W,
    const float* __restrict__ b, float* __restrict__ out)
{
    float* sW = smem;               // [128][WPAD]  W transposed: sW[k][o]
    float* sH = smem + 128 * WPAD;  // [128][HPAD]  H transposed: sH[k][node]

    int tid  = threadIdx.x;
    int lane = tid & 31;
    int warp = tid >> 5;
    int nodeBase = blockIdx.x * TM;

    // Stage W transposed. c = float4 chunk index along k (0..31).
    for (int c = warp; c < 32; c += 8) {
        #pragma unroll
        for (int ob = 0; ob < 128; ob += 32) {
            int o = ob + lane;
            float4 v = reinterpret_cast<const float4*>(W)[o * 32 + c];
            sW[(4 * c + 0) * WPAD + o] = v.x;
            sW[(4 * c + 1) * WPAD + o] = v.y;
            sW[(4 * c + 2) * WPAD + o] = v.z;
            sW[(4 * c + 3) * WPAD + o] = v.w;
        }
    }

    // Stage H transposed: k-chunks 0..15 come from x, 16..31 from g_neigh.
    for (int c = warp; c < 32; c += 8) {
        const float4* srcp = (c < 16) ? reinterpret_cast<const float4*>(x)
                                      : reinterpret_cast<const float4*>(g_neigh);
        #pragma unroll
        for (int nb = 0; nb < TM; nb += 32) {
            int node = nodeBase + nb + lane;
            float4 v;
            if (node < N_NODES) v = srcp[node * 16 + (c & 15)];
            else                v = make_float4(0.f, 0.f, 0.f, 0.f);
            int n = nb + lane;
            sH[(4 * c + 0) * HPAD + n] = v.x;
            sH[(4 * c + 1) * HPAD + n] = v.y;
            sH[(4 * c + 2) * HPAD + n] = v.z;
            sH[(4 * c + 3) * HPAD + n] = v.w;
        }
    }
    __syncthreads();

    int tx = tid & 15;   // output group: outs [tx*8, tx*8+8)
    int ty = tid >> 4;   // node group:   nodes [ty*4, ty*4+4)

    float acc[4][8];
    #pragma unroll
    for (int i = 0; i < 4; i++)
        #pragma unroll
        for (int j = 0; j < 8; j++) acc[i][j] = 0.f;

    #pragma unroll 4
    for (int k = 0; k < 128; k++) {
        float4 h  = *reinterpret_cast<float4*>(&sH[k * HPAD + ty * 4]);
        float4 w0 = *reinterpret_cast<float4*>(&sW[k * WPAD + tx * 8]);
        float4 w1 = *reinterpret_cast<float4*>(&sW[k * WPAD + tx * 8 + 4]);
        float hv[4] = {h.x, h.y, h.z, h.w};
        float wv[8] = {w0.x, w0.y, w0.z, w0.w, w1.x, w1.y, w1.z, w1.w};
        #pragma unroll
        for (int i = 0; i < 4; i++)
            #pragma unroll
            for (int j = 0; j < 8; j++)
                acc[i][j] += hv[i] * wv[j];
    }

    float bias[8];
    #pragma unroll
    for (int j = 0; j < 8; j++) bias[j] = b[tx * 8 + j];

    #pragma unroll
    for (int i = 0; i < 4; i++) {
        int node = nodeBase + ty * 4 + i;
        if (node < N_NODES) {
            float r[8];
            #pragma unroll
            for (int j = 0; j < 8; j++) {
                float v = acc[i][j] + bias[j];
                r[j] = v > 0.f ? v : 0.f;
            }
            float4* op = reinterpret_cast<float4*>(out + (size_t)node * HIDDEN + tx * 8);
            op[0] = make_float4(r[0], r[1], r[2], r[3]);
            op[1] = make_float4(r[4], r[5], r[6], r[7]);
        }
    }
}

extern "C" void kernel_launch(void* const* d_in, const int* in_sizes, int n_in,
                              void* d_out, int out_size) {
    const float* x  = (const float*)d_in[0];
    const int*   ei = (const int*)d_in[1];   // int32! (JAX x64 disabled)
    const float* W  = (const float*)d_in[2];
    const float* b  = (const float*)d_in[3];
    float*       out = (float*)d_out;

    zero_neigh<<<(N_NODES * D_FEAT / 4 + 255) / 256, 256>>>();

    int scatter_threads = N_EDGES * 16;
    scatter_add<<<(scatter_threads + 255) / 256, 256>>>(x, ei);

    int smem_bytes = (128 * WPAD + 128 * HPAD) * (int)sizeof(float);
    cudaFuncSetAttribute(fused_gemm,
                         cudaFuncAttributeMaxDynamicSharedMemorySize, smem_bytes);
    fused_gemm<<<(N_NODES + TM - 1) / TM, 256, smem_bytes>>>(x, W, b, out);
}

// round 3
// speedup vs baseline: 1.5339x; 1.5339x over previous
#include <cuda_runtime.h>

#define N_NODES 50000
#define D_FEAT 64
#define HIDDEN 128
#define N_EDGES 800000

// Scratch for aggregated neighbor features (no cudaMalloc allowed).
__device__ __align__(16) float g_neigh[N_NODES * D_FEAT];

__global__ void zero_neigh() {
    int i = blockIdx.x * blockDim.x + threadIdx.x;
    if (i < N_NODES * D_FEAT / 4)
        reinterpret_cast<float4*>(g_neigh)[i] = make_float4(0.f, 0.f, 0.f, 0.f);
}

// 16 threads per edge; each thread moves one float4 and issues ONE vector RED.
__global__ void scatter_add(const float* __restrict__ x,
                            const int* __restrict__ ei) {
    int tid = blockIdx.x * blockDim.x + threadIdx.x;
    int e = tid >> 4;
    if (e >= N_EDGES) return;
    int c = tid & 15;
    int src = ei[e];
    int dst = ei[N_EDGES + e];
    float4 v = reinterpret_cast<const float4*>(x)[src * 16 + c];
    float* o = g_neigh + dst * 64 + c * 4;
    asm volatile("red.global.add.v4.f32 [%0], {%1, %2, %3, %4};"
                 :: "l"(o), "f"(v.x), "f"(v.y), "f"(v.z), "f"(v.w)
                 : "memory");
}

// ---------------- fused concat + GEMM + bias + ReLU ----------------
// Tile: 64 nodes x 128 outputs per block, 256 threads.
// Inner product uses packed fma.rn.f32x2 (sm_100+): accumulators are
// output-pairs; W pairs come straight from LDS.128 bits; H is broadcast
// into both halves with one mov.b64 per (k, node).
#define TM 64
#define HPAD 68
#define WPAD 132

extern __shared__ float smem[];

__device__ __forceinline__ unsigned long long bcast_f32x2(float a) {
    unsigned long long r;
    asm("mov.b64 %0, {%1, %1};" : "=l"(r) : "f"(a));
    return r;
}

__global__ void __launch_bounds__(256, 2) fused_gemm(
    const float* __restrict__ x, const float* __restrict__ W,
    const float* __restrict__ b, float* __restrict__ out)
{
    float* sW = smem;               // [128][WPAD]  sW[k][o]
    float* sH = smem + 128 * WPAD;  // [128][HPAD]  sH[k][node]

    int tid  = threadIdx.x;
    int lane = tid & 31;
    int warp = tid >> 5;
    int nodeBase = blockIdx.x * TM;

    // Stage W transposed. c = float4 chunk index along k (0..31).
    for (int c = warp; c < 32; c += 8) {
        #pragma unroll
        for (int ob = 0; ob < 128; ob += 32) {
            int o = ob + lane;
            float4 v = reinterpret_cast<const float4*>(W)[o * 32 + c];
            sW[(4 * c + 0) * WPAD + o] = v.x;
            sW[(4 * c + 1) * WPAD + o] = v.y;
            sW[(4 * c + 2) * WPAD + o] = v.z;
            sW[(4 * c + 3) * WPAD + o] = v.w;
        }
    }

    // Stage H transposed: k-chunks 0..15 from x, 16..31 from g_neigh.
    for (int c = warp; c < 32; c += 8) {
        const float4* srcp = (c < 16) ? reinterpret_cast<const float4*>(x)
                                      : reinterpret_cast<const float4*>(g_neigh);
        #pragma unroll
        for (int nb = 0; nb < TM; nb += 32) {
            int node = nodeBase + nb + lane;
            float4 v;
            if (node < N_NODES) v = srcp[node * 16 + (c & 15)];
            else                v = make_float4(0.f, 0.f, 0.f, 0.f);
            int n = nb + lane;
            sH[(4 * c + 0) * HPAD + n] = v.x;
            sH[(4 * c + 1) * HPAD + n] = v.y;
            sH[(4 * c + 2) * HPAD + n] = v.z;
            sH[(4 * c + 3) * HPAD + n] = v.w;
        }
    }
    __syncthreads();

    int tx = tid & 15;   // outs [tx*8, tx*8+8)
    int ty = tid >> 4;   // nodes [ty*4, ty*4+4)

    // acc[i][jp] = packed pair of outputs {2jp, 2jp+1} for node i.
    unsigned long long acc[4][4];
    #pragma unroll
    for (int i = 0; i < 4; i++)
        #pragma unroll
        for (int jp = 0; jp < 4; jp++) acc[i][jp] = 0ull;

    const float* sHrow = &sH[ty * 4];
    const float* sWrow = &sW[tx * 8];

    #pragma unroll 4
    for (int k = 0; k < 128; k++) {
        float4 h = *reinterpret_cast<const float4*>(sHrow + k * HPAD);
        // 8 W values as 4 packed f32x2 (bit-identical reinterpret).
        ulonglong2 wa = *reinterpret_cast<const ulonglong2*>(sWrow + k * WPAD);
        ulonglong2 wb = *reinterpret_cast<const ulonglong2*>(sWrow + k * WPAD + 4);
        unsigned long long wv[4] = {wa.x, wa.y, wb.x, wb.y};
        float hv[4] = {h.x, h.y, h.z, h.w};
        #pragma unroll
        for (int i = 0; i < 4; i++) {
            unsigned long long hp = bcast_f32x2(hv[i]);
            #pragma unroll
            for (int jp = 0; jp < 4; jp++)
                asm("fma.rn.f32x2 %0, %1, %2, %0;"
                    : "+l"(acc[i][jp]) : "l"(hp), "l"(wv[jp]));
        }
    }

    float bias[8];
    #pragma unroll
    for (int j = 0; j < 8; j++) bias[j] = b[tx * 8 + j];

    #pragma unroll
    for (int i = 0; i < 4; i++) {
        int node = nodeBase + ty * 4 + i;
        if (node < N_NODES) {
            float r[8];
            #pragma unroll
            for (int jp = 0; jp < 4; jp++) {
                float lo, hi;
                asm("mov.b64 {%0, %1}, %2;" : "=f"(lo), "=f"(hi) : "l"(acc[i][jp]));
                float v0 = lo + bias[2 * jp];
                float v1 = hi + bias[2 * jp + 1];
                r[2 * jp]     = v0 > 0.f ? v0 : 0.f;
                r[2 * jp + 1] = v1 > 0.f ? v1 : 0.f;
            }
            float4* op = reinterpret_cast<float4*>(out + (size_t)node * HIDDEN + tx * 8);
            op[0] = make_float4(r[0], r[1], r[2], r[3]);
            op[1] = make_float4(r[4], r[5], r[6], r[7]);
        }
    }
}

extern "C" void kernel_launch(void* const* d_in, const int* in_sizes, int n_in,
                              void* d_out, int out_size) {
    const float* x  = (const float*)d_in[0];
    const int*   ei = (const int*)d_in[1];   // int32 (JAX x64 disabled)
    const float* W  = (const float*)d_in[2];
    const float* b  = (const float*)d_in[3];
    float*       out = (float*)d_out;

    zero_neigh<<<(N_NODES * D_FEAT / 4 + 255) / 256, 256>>>();

    int scatter_threads = N_EDGES * 16;
    scatter_add<<<(scatter_threads + 255) / 256, 256>>>(x, ei);

    int smem_bytes = (128 * WPAD + 128 * HPAD) * (int)sizeof(float);
    cudaFuncSetAttribute(fused_gemm,
                         cudaFuncAttributeMaxDynamicSharedMemorySize, smem_bytes);
    fused_gemm<<<(N_NODES + TM - 1) / TM, 256, smem_bytes>>>(x, W, b, out);
}